// round 1
// baseline (speedup 1.0000x reference)
#include <cuda_runtime.h>

// Problem constants
#define Gn    4
#define Mn    4096
#define Dn    128
#define NPG   16384           // queries per group (BS)
#define NTILE 128
#define MTILE 128

#define XQ_SIZE  (NPG * Gn * Dn)          // 8388608 floats: x_quant
#define IND_BASE (XQ_SIZE)                // + 65536 floats: indices (as float)
#define CNT_BASE (XQ_SIZE + NPG * Gn)     // + 16384 floats: new_count

// scratch: per-embedding squared norms (allocation-free device global)
__device__ float g_e2[Gn * Mn];

// ---------------------------------------------------------------------------
// prep: e2[g,m] = sum_k emb[g,m,k]^2  (one warp per row) + copy count -> out
// ---------------------------------------------------------------------------
__global__ void prep_kernel(const float* __restrict__ emb,
                            const float* __restrict__ count,
                            float* __restrict__ out) {
    int gtid = blockIdx.x * blockDim.x + threadIdx.x;
    int row  = gtid >> 5;            // warp id == embedding row (0..16383)
    int lane = threadIdx.x & 31;
    if (row < Gn * Mn) {
        float4 v = ((const float4*)(emb + (size_t)row * Dn))[lane];
        float s = v.x * v.x + v.y * v.y + v.z * v.z + v.w * v.w;
        #pragma unroll
        for (int o = 16; o; o >>= 1) s += __shfl_xor_sync(0xffffffffu, s, o);
        if (lane == 0) g_e2[row] = s;
    }
    if (gtid < Gn * Mn) out[CNT_BASE + gtid] = count[gtid];
}

// ---------------------------------------------------------------------------
// main: per CTA = (group g, 128-row n-tile). Loop m-tiles of 128, fp32 GEMM
// with 8x8 register blocking, argmin epilogue, then gather + histogram.
// ---------------------------------------------------------------------------
__global__ __launch_bounds__(256, 1)
void vq_kernel(const float* __restrict__ x,
               const float* __restrict__ emb,
               float* __restrict__ out) {
    extern __shared__ float smem[];
    float* Xs = smem;                 // [Dn][NTILE]  (k-major, 64 KB)
    float* Es = smem + Dn * NTILE;    // [Dn][MTILE]  (k-major, 64 KB)
    __shared__ int winner[NTILE];

    const int g   = blockIdx.y;
    const int n0  = blockIdx.x * NTILE;
    const int tid = threadIdx.x;
    const int ty  = tid >> 4;         // 0..15  (row group:  rows ty*8..ty*8+7)
    const int tx  = tid & 15;         // 0..15  (col group:  cols tx*8..tx*8+7)

    // ---- load X tile transposed into Xs[k][n] ----
    // x layout: (n, g, d) row-major -> vector (g, n) at ((n*Gn + g) * Dn)
    for (int i = tid; i < NTILE * 32; i += 256) {
        int n  = i & 127;
        int kv = i >> 7;              // 0..31 (float4 index along k)
        float4 v = *(const float4*)(x + ((size_t)(n0 + n) * Gn + g) * Dn + kv * 4);
        Xs[(kv * 4 + 0) * NTILE + n] = v.x;
        Xs[(kv * 4 + 1) * NTILE + n] = v.y;
        Xs[(kv * 4 + 2) * NTILE + n] = v.z;
        Xs[(kv * 4 + 3) * NTILE + n] = v.w;
    }

    float bestv[8];
    int   bestidx[8];
    #pragma unroll
    for (int i = 0; i < 8; i++) { bestv[i] = 3.4e38f; bestidx[i] = 0; }

    for (int m0 = 0; m0 < Mn; m0 += MTILE) {
        __syncthreads();
        // ---- load E tile transposed into Es[k][m] ----
        for (int i = tid; i < MTILE * 32; i += 256) {
            int m  = i & 127;
            int kv = i >> 7;
            float4 v = *(const float4*)(emb + ((size_t)g * Mn + m0 + m) * Dn + kv * 4);
            Es[(kv * 4 + 0) * MTILE + m] = v.x;
            Es[(kv * 4 + 1) * MTILE + m] = v.y;
            Es[(kv * 4 + 2) * MTILE + m] = v.z;
            Es[(kv * 4 + 3) * MTILE + m] = v.w;
        }
        __syncthreads();

        float acc[8][8];
        #pragma unroll
        for (int i = 0; i < 8; i++)
            #pragma unroll
            for (int j = 0; j < 8; j++) acc[i][j] = 0.0f;

        #pragma unroll 4
        for (int k = 0; k < Dn; k++) {
            float a[8], b[8];
            *(float4*)(a)     = *(const float4*)(Xs + k * NTILE + ty * 8);
            *(float4*)(a + 4) = *(const float4*)(Xs + k * NTILE + ty * 8 + 4);
            *(float4*)(b)     = *(const float4*)(Es + k * MTILE + tx * 8);
            *(float4*)(b + 4) = *(const float4*)(Es + k * MTILE + tx * 8 + 4);
            #pragma unroll
            for (int i = 0; i < 8; i++)
                #pragma unroll
                for (int j = 0; j < 8; j++)
                    acc[i][j] = fmaf(a[i], b[j], acc[i][j]);
        }

        // ---- argmin epilogue: score = e2 - 2*dot (x^2 is row-constant) ----
        #pragma unroll
        for (int j = 0; j < 8; j++) {
            int   midx = m0 + tx * 8 + j;
            float e2   = g_e2[g * Mn + midx];
            #pragma unroll
            for (int i = 0; i < 8; i++) {
                float s = fmaf(-2.0f, acc[i][j], e2);
                if (s < bestv[i]) { bestv[i] = s; bestidx[i] = midx; }
            }
        }
    }
    __syncthreads();

    // ---- cross-thread reduction (16 candidates per row), reuse Xs ----
    float* rv = Xs;                           // [128][16]
    int*   ri = (int*)(Xs + NTILE * 16);      // [128][16]
    #pragma unroll
    for (int i = 0; i < 8; i++) {
        rv[(ty * 8 + i) * 16 + tx] = bestv[i];
        ri[(ty * 8 + i) * 16 + tx] = bestidx[i];
    }
    __syncthreads();

    if (tid < NTILE) {
        int row = tid;
        float bv = rv[row * 16];
        int   bi = ri[row * 16];
        #pragma unroll
        for (int t = 1; t < 16; t++) {
            float v  = rv[row * 16 + t];
            int   id = ri[row * 16 + t];
            if (v < bv || (v == bv && id < bi)) { bv = v; bi = id; }
        }
        winner[row] = bi;
        int nglob = n0 + row;
        out[IND_BASE + (size_t)nglob * Gn + g] = (float)bi;          // index
        atomicAdd(&out[CNT_BASE + g * Mn + bi], 1.0f);               // histogram
    }
    __syncthreads();

    // ---- gather x_quant: copy winning embedding rows (coalesced) ----
    for (int i = tid; i < NTILE * 32; i += 256) {
        int row = i >> 5;
        int c4  = i & 31;
        int bi  = winner[row];
        float4 v = *(const float4*)(emb + ((size_t)g * Mn + bi) * Dn + c4 * 4);
        *(float4*)(out + ((size_t)(n0 + row) * Gn + g) * Dn + c4 * 4) = v;
    }
}

// ---------------------------------------------------------------------------
extern "C" void kernel_launch(void* const* d_in, const int* in_sizes, int n_in,
                              void* d_out, int out_size) {
    const float* x     = (const float*)d_in[0];
    const float* emb   = (const float*)d_in[1];
    const float* count = (const float*)d_in[2];
    float*       out   = (float*)d_out;

    const int smem_bytes = 2 * Dn * NTILE * (int)sizeof(float);   // 128 KB
    cudaFuncSetAttribute(vq_kernel,
                         cudaFuncAttributeMaxDynamicSharedMemorySize, smem_bytes);

    // prep: 16384 warps (one per embedding row) + count copy
    prep_kernel<<<(Gn * Mn * 32 + 255) / 256, 256>>>(emb, count, out);

    dim3 grid(NPG / NTILE, Gn);
    vq_kernel<<<grid, 256, smem_bytes>>>(x, emb, out);
}